// round 16
// baseline (speedup 1.0000x reference)
#include <cuda_runtime.h>
#include <cuda_fp16.h>
#include <math.h>
#include <stdint.h>

// ---------------- problem constants ----------------
#define D_MODEL 768
#define N_HEADS 12
#define D_HEAD  64
#define D_MLP   3072
#define BATCH   2
#define SEQ     2048
#define ROWS    (BATCH*SEQ)          // 4096
#define QKV_N   (3*D_MODEL)          // 2304

// ---------------- device scratch ----------------
__device__ __half g_x1h   [ROWS * D_MODEL];
__device__ __half g_qkvh  [ROWS * QKV_N];
__device__ __half g_zh    [ROWS * D_MODEL];
__device__ float  g_mid   [ROWS * D_MODEL];
__device__ __half g_x2h   [ROWS * D_MODEL];
__device__ __half g_hidh  [ROWS * D_MLP];
__device__ __half g_wqkvh [D_MODEL * QKV_N];
__device__ float  g_bqkv  [QKV_N];
__device__ __half g_woh   [D_MODEL * D_MODEL];
__device__ __half g_winh  [D_MODEL * D_MLP];
__device__ __half g_wouth [D_MLP * D_MODEL];

// ---------------- helpers ----------------
__device__ __forceinline__ uint32_t smem_u32(const void* p) {
    uint32_t a;
    asm("{ .reg .u64 t; cvta.to.shared.u64 t, %1; cvt.u32.u64 %0, t; }" : "=r"(a) : "l"(p));
    return a;
}
__device__ __forceinline__ float fast_tanh(float x) {
    float y; asm("tanh.approx.f32 %0, %1;" : "=f"(y) : "f"(x)); return y;
}
__device__ __forceinline__ float gelu_new_f(float x) {
    const float c = 0.7978845608028654f;
    float x3 = x * x * x;
    return 0.5f * x * (1.0f + fast_tanh(c * (x + 0.044715f * x3)));
}
__device__ __forceinline__ void mma_f16(float& c0, float& c1, float& c2, float& c3,
                                        uint32_t a0, uint32_t a1, uint32_t a2, uint32_t a3,
                                        uint32_t b0, uint32_t b1) {
    asm volatile(
        "mma.sync.aligned.m16n8k16.row.col.f32.f16.f16.f32 "
        "{%0,%1,%2,%3}, {%4,%5,%6,%7}, {%8,%9}, {%0,%1,%2,%3};\n"
        : "+f"(c0), "+f"(c1), "+f"(c2), "+f"(c3)
        : "r"(a0), "r"(a1), "r"(a2), "r"(a3), "r"(b0), "r"(b1));
}
__device__ __forceinline__ void ldm_x4(uint32_t& r0, uint32_t& r1, uint32_t& r2, uint32_t& r3,
                                       uint32_t a) {
    asm volatile("ldmatrix.sync.aligned.m8n8.x4.shared.b16 {%0,%1,%2,%3}, [%4];"
                 : "=r"(r0), "=r"(r1), "=r"(r2), "=r"(r3) : "r"(a));
}
__device__ __forceinline__ void ldm_x4t(uint32_t& r0, uint32_t& r1, uint32_t& r2, uint32_t& r3,
                                        uint32_t a) {
    asm volatile("ldmatrix.sync.aligned.m8n8.x4.trans.shared.b16 {%0,%1,%2,%3}, [%4];"
                 : "=r"(r0), "=r"(r1), "=r"(r2), "=r"(r3) : "r"(a));
}
__device__ __forceinline__ void cp16(uint32_t dst, const void* src) {
    asm volatile("cp.async.cg.shared.global [%0], [%1], 16;" :: "r"(dst), "l"(src));
}
#define CP_COMMIT() asm volatile("cp.async.commit_group;" ::: "memory")
#define CP_WAIT1()  asm volatile("cp.async.wait_group 1;" ::: "memory")
#define CP_WAIT0()  asm volatile("cp.async.wait_group 0;" ::: "memory")

__device__ __forceinline__ uint32_t h2u(__half2 h) { return *(uint32_t*)&h; }

// combined (sum, sumsq) block reduction for 256 threads
__device__ __forceinline__ float2 block_sum2_256(float a, float b) {
    __shared__ float reda[8], redb[8];
    __shared__ float2 total;
    #pragma unroll
    for (int m = 16; m >= 1; m >>= 1) {
        a += __shfl_xor_sync(0xffffffffu, a, m);
        b += __shfl_xor_sync(0xffffffffu, b, m);
    }
    int w = threadIdx.x >> 5;
    if ((threadIdx.x & 31) == 0) { reda[w] = a; redb[w] = b; }
    __syncthreads();
    if (threadIdx.x < 8) {
        float ta = reda[threadIdx.x], tb = redb[threadIdx.x];
        #pragma unroll
        for (int m = 4; m >= 1; m >>= 1) {
            ta += __shfl_xor_sync(0xffu, ta, m);
            tb += __shfl_xor_sync(0xffu, tb, m);
        }
        if (threadIdx.x == 0) total = make_float2(ta, tb);
    }
    __syncthreads();
    return total;
}

// ---------------- fused weight prep + LN1 ----------------------------------------
#define PK_QKV_BLK 864
#define PK_WO_BLK  288
#define PK_WIN_BLK 1152
#define PK_W_BLK (PK_QKV_BLK + PK_WO_BLK + 2 * PK_WIN_BLK)
#define PK_TOTAL_BLK (PK_W_BLK + ROWS)

__device__ __forceinline__ void f2h_chunk(const float* __restrict__ s,
                                          __half* __restrict__ d, int i) {
    float4 v0 = *(const float4*)(s + (size_t)i * 8);
    float4 v1 = *(const float4*)(s + (size_t)i * 8 + 4);
    __half2 h[4];
    h[0] = __floats2half2_rn(v0.x, v0.y);
    h[1] = __floats2half2_rn(v0.z, v0.w);
    h[2] = __floats2half2_rn(v1.x, v1.y);
    h[3] = __floats2half2_rn(v1.z, v1.w);
    *(uint4*)(d + (size_t)i * 8) = *(uint4*)h;
}

__global__ void prep_all(const float* __restrict__ WQ, const float* __restrict__ WK,
                         const float* __restrict__ WV, const float* __restrict__ bQ,
                         const float* __restrict__ bK, const float* __restrict__ bV,
                         const float* __restrict__ WO, const float* __restrict__ Win,
                         const float* __restrict__ Wout,
                         const float* __restrict__ resid_pre,
                         const float* __restrict__ ln1w, const float* __restrict__ ln1b,
                         __half* __restrict__ Wp, float* __restrict__ bp,
                         __half* __restrict__ woh, __half* __restrict__ winh,
                         __half* __restrict__ wouth, __half* __restrict__ x1h) {
    int blk = blockIdx.x;
    if (blk < PK_QKV_BLK) {
        int idx = blk * 256 + threadIdx.x;
        int hd = (idx & 7) * 8;
        int t  = idx >> 3;
        int e  = t % D_MODEL;
        int t2 = t / D_MODEL;
        int n  = t2 % N_HEADS;
        int which = t2 / N_HEADS;
        const float* W = (which == 0) ? WQ : (which == 1) ? WK : WV;
        const float* src = W + ((size_t)n * D_MODEL + e) * D_HEAD + hd;
        float4 v0 = *(const float4*)(src);
        float4 v1 = *(const float4*)(src + 4);
        __half2 h[4];
        h[0] = __floats2half2_rn(v0.x, v0.y);
        h[1] = __floats2half2_rn(v0.z, v0.w);
        h[2] = __floats2half2_rn(v1.x, v1.y);
        h[3] = __floats2half2_rn(v1.z, v1.w);
        *(uint4*)(Wp + (size_t)e * QKV_N + which * D_MODEL + n * D_HEAD + hd) = *(uint4*)h;
        if (idx < QKV_N) {
            int w2 = idx / D_MODEL;
            int c = idx - w2 * D_MODEL;
            const float* bb = (w2 == 0) ? bQ : (w2 == 1) ? bK : bV;
            bp[idx] = bb[c];
        }
        return;
    }
    blk -= PK_QKV_BLK;
    if (blk < PK_WO_BLK) { f2h_chunk(WO, woh, blk * 256 + threadIdx.x); return; }
    blk -= PK_WO_BLK;
    if (blk < PK_WIN_BLK) { f2h_chunk(Win, winh, blk * 256 + threadIdx.x); return; }
    blk -= PK_WIN_BLK;
    if (blk < PK_WIN_BLK) { f2h_chunk(Wout, wouth, blk * 256 + threadIdx.x); return; }
    blk -= PK_WIN_BLK;
    {
        int row = blk;
        const float* xr = resid_pre + (size_t)row * D_MODEL;
        __half* yr = x1h + (size_t)row * D_MODEL;
        int tid = threadIdx.x;
        float v0 = xr[tid], v1 = xr[tid + 256], v2 = xr[tid + 512];
        float2 ss = block_sum2_256(v0 + v1 + v2, v0 * v0 + v1 * v1 + v2 * v2);
        float mean = ss.x * (1.0f / D_MODEL);
        float var = ss.y * (1.0f / D_MODEL) - mean * mean;
        float rstd = rsqrtf(var + 1e-5f);
        yr[tid]       = __float2half_rn((v0 - mean) * rstd * ln1w[tid]       + ln1b[tid]);
        yr[tid + 256] = __float2half_rn((v1 - mean) * rstd * ln1w[tid + 256] + ln1b[tid + 256]);
        yr[tid + 512] = __float2half_rn((v2 - mean) * rstd * ln1w[tid + 512] + ln1b[tid + 512]);
    }
}

// ---------------- layernorm (LN2) -------------------------------------------------
__global__ void ln_kernel_h(const float* __restrict__ x, const float* __restrict__ w,
                            const float* __restrict__ b, __half* __restrict__ y) {
    int row = blockIdx.x;
    const float* xr = x + (size_t)row * D_MODEL;
    __half* yr = y + (size_t)row * D_MODEL;
    int tid = threadIdx.x;
    float v0 = xr[tid], v1 = xr[tid + 256], v2 = xr[tid + 512];
    float2 ss = block_sum2_256(v0 + v1 + v2, v0 * v0 + v1 * v1 + v2 * v2);
    float mean = ss.x * (1.0f / D_MODEL);
    float var = ss.y * (1.0f / D_MODEL) - mean * mean;
    float rstd = rsqrtf(var + 1e-5f);
    yr[tid]       = __float2half_rn((v0 - mean) * rstd * w[tid]       + b[tid]);
    yr[tid + 256] = __float2half_rn((v1 - mean) * rstd * w[tid + 256] + b[tid + 256]);
    yr[tid + 512] = __float2half_rn((v2 - mean) * rstd * w[tid + 512] + b[tid + 512]);
}

// ---------------- fp16 GEMM, BM=128 x BN=128, fragment-pipelined, 2 CTAs/SM ------
#define GH_STG 32768
#define GH_SMEM (3 * GH_STG)

template<int GELU, int RES, int OUTH>
__global__ __launch_bounds__(256, 2) void gemm_hp(
        const __half* __restrict__ A, const __half* __restrict__ B,
        const float* __restrict__ bias, const float* __restrict__ res,
        void* __restrict__ Cv, int M, int N, int K) {
    extern __shared__ char sm8[];
    const uint32_t sb = smem_u32(sm8);

    const int tid = threadIdx.x;
    const int lane = tid & 31;
    const int wid = tid >> 5;
    const int lr = lane >> 2;
    const int lc = lane & 3;
    const int warp_m = wid & 1;
    const int warp_n = wid >> 1;
    const int bm = blockIdx.y * 128;
    const int bn = blockIdx.x * 128;

    float acc[4][4][4];
    #pragma unroll
    for (int i = 0; i < 4; i++)
        #pragma unroll
        for (int j = 0; j < 4; j++)
            #pragma unroll
            for (int u = 0; u < 4; u++) acc[i][j][u] = 0.0f;

    const int nt = K / 64;

    auto issue = [&](int s, int bk) {
        uint32_t ab = sb + (uint32_t)s * GH_STG;
        #pragma unroll
        for (int i = 0; i < 4; i++) {
            int idx = tid + i * 256;
            int rr = idx >> 3, c = idx & 7;
            cp16(ab + (uint32_t)(rr * 128 + ((c ^ (rr & 7)) * 16)),
                 A + (size_t)(bm + rr) * K + bk + c * 8);
        }
        uint32_t bb = ab + 16384;
        #pragma unroll
        for (int i = 0; i < 4; i++) {
            int idx = tid + i * 256;
            int rr = idx >> 4, c = idx & 15;
            int sc = (c & 8) | ((c ^ rr) & 7);
            cp16(bb + (uint32_t)(rr * 256 + sc * 16),
                 B + (size_t)(bk + rr) * N + bn + c * 8);
        }
    };

    issue(0, 0);  CP_COMMIT();
    issue(1, 64); CP_COMMIT();

    const int j8 = lane >> 3;
    const int li = lane & 7;

    auto load_a = [&](uint32_t Ab, int ks, uint32_t a[4][4]) {
        #pragma unroll
        for (int i = 0; i < 4; i++) {
            int row = warp_m * 64 + i * 16 + (j8 & 1) * 8 + li;
            int chunk = ks * 2 + (j8 >> 1);
            ldm_x4(a[i][0], a[i][1], a[i][2], a[i][3],
                   Ab + (uint32_t)(row * 128 + ((chunk ^ (row & 7)) * 16)));
        }
    };
    auto load_b = [&](uint32_t Bb, int ks, uint32_t b[2][4]) {
        #pragma unroll
        for (int jn = 0; jn < 2; jn++) {
            int krow = ks * 16 + (j8 & 1) * 8 + li;
            int nch = warp_n * 4 + jn * 2 + (j8 >> 1);
            int sc = (nch & 8) | ((nch ^ krow) & 7);
            ldm_x4t(b[jn][0], b[jn][1], b[jn][2], b[jn][3],
                    Bb + (uint32_t)(krow * 256 + sc * 16));
        }
    };

    for (int t = 0; t < nt; t++) {
        CP_WAIT1();
        __syncthreads();
        if (t + 2 < nt) issue((t + 2) % 3, (t + 2) * 64);
        CP_COMMIT();

        const uint32_t Ab = sb + (uint32_t)(t % 3) * GH_STG;
        const uint32_t Bb = Ab + 16384;

        uint32_t fa[2][4][4];
        uint32_t fb[2][2][4];
        load_a(Ab, 0, fa[0]);
        load_b(Bb, 0, fb[0]);

        #pragma unroll
        for (int ks = 0; ks < 4; ks++) {
            const int cur = ks & 1;
            const int nxt = cur ^ 1;
            if (ks < 3) {
                load_a(Ab, ks + 1, fa[nxt]);
                load_b(Bb, ks + 1, fb[nxt]);
            }
            #pragma unroll
            for (int i = 0; i < 4; i++)
                #pragma unroll
                for (int n8 = 0; n8 < 4; n8++) {
                    int jn = n8 >> 1, sub = n8 & 1;
                    mma_f16(acc[i][n8][0], acc[i][n8][1], acc[i][n8][2], acc[i][n8][3],
                            fa[cur][i][0], fa[cur][i][1], fa[cur][i][2], fa[cur][i][3],
                            fb[cur][jn][sub * 2], fb[cur][jn][sub * 2 + 1]);
                }
        }
        __syncthreads();
    }
    CP_WAIT0();

    float* Cf = (float*)Cv;
    __half* Ch = (__half*)Cv;
    #pragma unroll
    for (int i = 0; i < 4; i++) {
        #pragma unroll
        for (int n8 = 0; n8 < 4; n8++) {
            int r0 = bm + warp_m * 64 + i * 16 + lr;
            int cc = bn + warp_n * 32 + n8 * 8 + lc * 2;
            float2 bv = *(const float2*)&bias[cc];
            #pragma unroll
            for (int hrow = 0; hrow < 2; hrow++) {
                int r = r0 + hrow * 8;
                float o0 = acc[i][n8][hrow * 2]     + bv.x;
                float o1 = acc[i][n8][hrow * 2 + 1] + bv.y;
                if (GELU) { o0 = gelu_new_f(o0); o1 = gelu_new_f(o1); }
                if (RES) {
                    float2 rv = *(const float2*)&res[(size_t)r * N + cc];
                    o0 += rv.x; o1 += rv.y;
                }
                if (OUTH) {
                    __half2 h = __floats2half2_rn(o0, o1);
                    *(__half2*)&Ch[(size_t)r * N + cc] = h;
                } else {
                    *(float2*)&Cf[(size_t)r * N + cc] = make_float2(o0, o1);
                }
            }
        }
    }
}

// ---------------- fp16 MMA flash attention, BQ=64, 128 threads, 4 CTAs/SM --------
#define A64_Q   8192
#define A64_STG 16384
#define A64_SMEM (A64_Q + 2 * A64_STG)

__global__ __launch_bounds__(128, 4) void attn_h64_kernel(const __half* __restrict__ qkv,
                                                          __half* __restrict__ z) {
    const int qt = (SEQ / 64 - 1) - blockIdx.x;
    const int bh = blockIdx.y;
    const int b = bh / N_HEADS;
    const int h = bh - b * N_HEADS;

    extern __shared__ char sm8[];
    const uint32_t sb = smem_u32(sm8);
    const uint32_t stg = sb + A64_Q;

    const int tid = threadIdx.x;
    const int lane = tid & 31;
    const int wid = tid >> 5;
    const int lr = lane >> 2;
    const int lc = lane & 3;
    const int j8 = lane >> 3;
    const int li = lane & 7;

    const size_t rowbase = (size_t)b * SEQ;
    const __half* qb = qkv + rowbase * QKV_N + h * 64;
    const __half* kb = qb + D_MODEL;
    const __half* vb = qb + 2 * D_MODEL;

    {
        const __half2 sc2 = __floats2half2_rn(0.125f, 0.125f);
        #pragma unroll
        for (int i = 0; i < 4; i++) {
            int idx = tid + i * 128;
            int r = idx >> 3, c = idx & 7;
            uint4 raw = *(const uint4*)(qb + (size_t)(qt * 64 + r) * QKV_N + c * 8);
            __half2* hp = (__half2*)&raw;
            hp[0] = __hmul2(hp[0], sc2); hp[1] = __hmul2(hp[1], sc2);
            hp[2] = __hmul2(hp[2], sc2); hp[3] = __hmul2(hp[3], sc2);
            *(uint4*)(sm8 + r * 128 + ((c ^ (r & 7)) * 16)) = raw;
        }
    }
    __syncthreads();

    uint32_t qa[4][4];
    {
        int row = wid * 16 + (j8 & 1) * 8 + li;
        uint32_t rb_ = sb + row * 128;
        #pragma unroll
        for (int ks = 0; ks < 4; ks++) {
            int ch = ks * 2 + (j8 >> 1);
            ldm_x4(qa[ks][0], qa[ks][1], qa[ks][2], qa[ks][3],
                   rb_ + ((ch ^ (row & 7)) * 16));
        }
    }

    const int row0 = qt * 64 + wid * 16 + lr;
    const int row1 = row0 + 8;

    float m0 = -INFINITY, m1 = -INFINITY, l0 = 0.0f, l1 = 0.0f;
    float o[8][4];
    #pragma unroll
    for (int n = 0; n < 8; n++) { o[n][0] = o[n][1] = o[n][2] = o[n][3] = 0.0f; }

    const int nkt = qt + 1;

    auto issue = [&](int s, int kt) {
        uint32_t base = stg + (uint32_t)s * A64_STG;
        #pragma unroll
        for (int i = 0; i < 4; i++) {
            int idx = tid + i * 128;
            int r = idx >> 3, c = idx & 7;
            uint32_t off = r * 128 + ((c ^ (r & 7)) * 16);
            size_t grow = (size_t)(kt * 64 + r) * QKV_N + c * 8;
            cp16(base + off,        kb + grow);
            cp16(base + 8192 + off, vb + grow);
        }
    };

    issue(0, 0); CP_COMMIT();

    for (int kt = 0; kt < nkt; kt++) {
        __syncthreads();
        if (kt + 1 < nkt) {
            issue((kt + 1) & 1, kt + 1);
            CP_COMMIT();
            CP_WAIT1();
        } else {
            CP_WAIT0();
        }
        __syncthreads();

        const uint32_t Kb = stg + (uint32_t)(kt & 1) * A64_STG;
        const uint32_t Vb = Kb + 8192;
        const bool do_mask = (kt == qt);

        #pragma unroll
        for (int hf = 0; hf < 2; hf++) {
            float s[4][4];
            #pragma unroll
            for (int n = 0; n < 4; n++) { s[n][0] = s[n][1] = s[n][2] = s[n][3] = 0.0f; }
            #pragma unroll
            for (int ks = 0; ks < 4; ks++) {
                #pragma unroll
                for (int ng = 0; ng < 2; ng++) {
                    int row = hf * 32 + ng * 16 + (j8 & 1) * 8 + li;
                    int ch = ks * 2 + (j8 >> 1);
                    uint32_t k0, k1, k2, k3;
                    ldm_x4(k0, k1, k2, k3, Kb + row * 128 + ((ch ^ (row & 7)) * 16));
                    mma_f16(s[ng * 2][0], s[ng * 2][1], s[ng * 2][2], s[ng * 2][3],
                            qa[ks][0], qa[ks][1], qa[ks][2], qa[ks][3], k0, k2);
                    mma_f16(s[ng * 2 + 1][0], s[ng * 2 + 1][1], s[ng * 2 + 1][2], s[ng * 2 + 1][3],
                            qa[ks][0], qa[ks][1], qa[ks][2], qa[ks][3], k1, k3);
                }
            }

            if (do_mask) {
                const int kbase = kt * 64 + hf * 32 + lc * 2;
                #pragma unroll
                for (int n8 = 0; n8 < 4; n8++) {
                    int key0 = kbase + n8 * 8;
                    int key1 = key0 + 1;
                    if (key0 > row0) s[n8][0] = -1e30f;
                    if (key1 > row0) s[n8][1] = -1e30f;
                    if (key0 > row1) s[n8][2] = -1e30f;
                    if (key1 > row1) s[n8][3] = -1e30f;
                }
            }

            float tm0 = -INFINITY, tm1 = -INFINITY;
            #pragma unroll
            for (int n8 = 0; n8 < 4; n8++) {
                tm0 = fmaxf(tm0, fmaxf(s[n8][0], s[n8][1]));
                tm1 = fmaxf(tm1, fmaxf(s[n8][2], s[n8][3]));
            }
            tm0 = fmaxf(tm0, __shfl_xor_sync(0xffffffffu, tm0, 1));
            tm0 = fmaxf(tm0, __shfl_xor_sync(0xffffffffu, tm0, 2));
            tm1 = fmaxf(tm1, __shfl_xor_sync(0xffffffffu, tm1, 1));
            tm1 = fmaxf(tm1, __shfl_xor_sync(0xffffffffu, tm1, 2));
            float nm0 = fmaxf(m0, tm0), nm1 = fmaxf(m1, tm1);
            float a0 = __expf(m0 - nm0), a1 = __expf(m1 - nm1);
            m0 = nm0; m1 = nm1;

            float ts0 = 0.0f, ts1 = 0.0f;
            uint32_t ph[4][2];
            #pragma unroll
            for (int n8 = 0; n8 < 4; n8++) {
                float p0 = __expf(s[n8][0] - nm0);
                float p1 = __expf(s[n8][1] - nm0);
                float p2 = __expf(s[n8][2] - nm1);
                float p3 = __expf(s[n8][3] - nm1);
                ts0 += p0 + p1;
                ts1 += p2 + p3;
                ph[n8][0] = h2u(__floats2half2_rn(p0, p1));
                ph[n8][1] = h2u(__floats2half2_rn(p2, p3));
            }
            ts0 += __shfl_xor_sync(0xffffffffu, ts0, 1);
            ts0 += __shfl_xor_sync(0xffffffffu, ts0, 2);
            ts1 += __shfl_xor_sync(0xffffffffu, ts1, 1);
            ts1 += __shfl_xor_sync(0xffffffffu, ts1, 2);
            l0 = l0 * a0 + ts0;
            l1 = l1 * a1 + ts1;
            #pragma unroll
            for (int n8 = 0; n8 < 8; n8++) {
                o[n8][0] *= a0; o[n8][1] *= a0;
                o[n8][2] *= a1; o[n8][3] *= a1;
            }

            #pragma unroll
            for (int ks = 0; ks < 2; ks++) {
                uint32_t pa0 = ph[ks * 2][0];
                uint32_t pa1 = ph[ks * 2][1];
                uint32_t pa2 = ph[ks * 2 + 1][0];
                uint32_t pa3 = ph[ks * 2 + 1][1];
                #pragma unroll
                for (int vg = 0; vg < 4; vg++) {
                    int krow = hf * 32 + ks * 16 + (j8 & 1) * 8 + li;
                    int nch = vg * 2 + (j8 >> 1);
                    uint32_t v0, v1, v2, v3;
                    ldm_x4t(v0, v1, v2, v3, Vb + krow * 128 + ((nch ^ (krow & 7)) * 16));
                    mma_f16(o[vg * 2][0], o[vg * 2][1], o[vg * 2][2], o[vg * 2][3],
                            pa0, pa1, pa2, pa3, v0, v1);
                    mma_f16(o[vg * 2 + 1][0], o[vg * 2 + 1][1], o[vg * 2 + 1][2], o[vg * 2 + 1][3],
                            pa0, pa1, pa2, pa3, v2, v3);
                }
            }
        }
    }

    float inv0 = 1.0f / l0, inv1 = 1.0f / l1;
    __half* z0 = z + (rowbase + row0) * D_MODEL + h * 64 + lc * 2;
    __half* z1 = z + (rowbase + row1) * D_MODEL + h * 64 + lc * 2;
    #pragma unroll
    for (int n8 = 0; n8 < 8; n8++) {
        *(__half2*)(z0 + n8 * 8) = __floats2half2_rn(o[n8][0] * inv0, o[n8][1] * inv0);
        *(__half2*)(z1 + n8 * 8) = __floats2half2_rn(o[n8][2] * inv1, o[n8][3] * inv1);
    }
}

// ---------------- launch ----------------
extern "C" void kernel_launch(void* const* d_in, const int* in_sizes, int n_in,
                              void* d_out, int out_size) {
    const float* resid_pre = (const float*)d_in[0];
    const float* WQ   = (const float*)d_in[1];
    const float* bQ   = (const float*)d_in[2];
    const float* WK   = (const float*)d_in[3];
    const float* bK   = (const float*)d_in[4];
    const float* WV   = (const float*)d_in[5];
    const float* bV   = (const float*)d_in[6];
    const float* WO   = (const float*)d_in[7];
    const float* bO   = (const float*)d_in[8];
    const float* ln1w = (const float*)d_in[9];
    const float* ln1b = (const float*)d_in[10];
    const float* ln2w = (const float*)d_in[11];
    const float* ln2b = (const float*)d_in[12];
    const float* Win  = (const float*)d_in[13];
    const float* bin  = (const float*)d_in[14];
    const float* Wout = (const float*)d_in[15];
    const float* bout = (const float*)d_in[16];
    float* out = (float*)d_out;

    __half *x1h, *qkvh, *zh, *x2h, *hidh, *wqkvh, *woh, *winh, *wouth;
    float *mid, *bp;
    cudaGetSymbolAddress((void**)&x1h,    g_x1h);
    cudaGetSymbolAddress((void**)&qkvh,   g_qkvh);
    cudaGetSymbolAddress((void**)&zh,     g_zh);
    cudaGetSymbolAddress((void**)&mid,    g_mid);
    cudaGetSymbolAddress((void**)&x2h,    g_x2h);
    cudaGetSymbolAddress((void**)&hidh,   g_hidh);
    cudaGetSymbolAddress((void**)&wqkvh,  g_wqkvh);
    cudaGetSymbolAddress((void**)&bp,     g_bqkv);
    cudaGetSymbolAddress((void**)&woh,    g_woh);
    cudaGetSymbolAddress((void**)&winh,   g_winh);
    cudaGetSymbolAddress((void**)&wouth,  g_wouth);

    cudaFuncSetAttribute(attn_h64_kernel, cudaFuncAttributeMaxDynamicSharedMemorySize, A64_SMEM);
    cudaFuncSetAttribute(gemm_hp<0,0,1>,  cudaFuncAttributeMaxDynamicSharedMemorySize, GH_SMEM);
    cudaFuncSetAttribute(gemm_hp<1,0,1>,  cudaFuncAttributeMaxDynamicSharedMemorySize, GH_SMEM);
    cudaFuncSetAttribute(gemm_hp<0,1,0>,  cudaFuncAttributeMaxDynamicSharedMemorySize, GH_SMEM);

    // fused weight prep + LN1 (single launch)
    prep_all<<<PK_TOTAL_BLK, 256>>>(WQ, WK, WV, bQ, bK, bV, WO, Win, Wout,
                                    resid_pre, ln1w, ln1b,
                                    wqkvh, bp, woh, winh, wouth, x1h);

    // QKV projection -> half (BM=128, fragment-pipelined)
    gemm_hp<0,0,1><<<dim3(QKV_N / 128, ROWS / 128), 256, GH_SMEM>>>(
        x1h, wqkvh, bp, nullptr, qkvh, ROWS, QKV_N, D_MODEL);
    // attention -> half z (BQ=64, 4 CTAs/SM)
    attn_h64_kernel<<<dim3(SEQ / 64, BATCH * N_HEADS), 128, A64_SMEM>>>(qkvh, zh);
    // O projection + residual -> float mid (BM=128, fragment-pipelined)
    gemm_hp<0,1,0><<<dim3(D_MODEL / 128, ROWS / 128), 256, GH_SMEM>>>(
        zh, woh, bO, resid_pre, mid, ROWS, D_MODEL, D_MODEL);
    // LN2 -> half
    ln_kernel_h<<<ROWS, 256>>>(mid, ln2w, ln2b, x2h);
    // MLP up + gelu -> half (BM=128, fragment-pipelined)
    gemm_hp<1,0,1><<<dim3(D_MLP / 128, ROWS / 128), 256, GH_SMEM>>>(
        x2h, winh, bin, nullptr, hidh, ROWS, D_MLP, D_MODEL);
    // MLP down + residual -> float out (BM=128, fragment-pipelined)
    gemm_hp<0,1,0><<<dim3(D_MODEL / 128, ROWS / 128), 256, GH_SMEM>>>(
        hidh, wouth, bout, mid, out, ROWS, D_MODEL, D_MLP);
}

// round 17
// speedup vs baseline: 1.0347x; 1.0347x over previous
#include <cuda_runtime.h>
#include <cuda_fp16.h>
#include <math.h>
#include <stdint.h>

// ---------------- problem constants ----------------
#define D_MODEL 768
#define N_HEADS 12
#define D_HEAD  64
#define D_MLP   3072
#define BATCH   2
#define SEQ     2048
#define ROWS    (BATCH*SEQ)          // 4096
#define QKV_N   (3*D_MODEL)          // 2304

// ---------------- device scratch ----------------
__device__ __half g_x1h   [ROWS * D_MODEL];
__device__ __half g_qkvh  [ROWS * QKV_N];
__device__ __half g_zh    [ROWS * D_MODEL];
__device__ float  g_mid   [ROWS * D_MODEL];
__device__ __half g_x2h   [ROWS * D_MODEL];
__device__ __half g_hidh  [ROWS * D_MLP];
__device__ __half g_wqkvh [D_MODEL * QKV_N];
__device__ float  g_bqkv  [QKV_N];
__device__ __half g_woh   [D_MODEL * D_MODEL];
__device__ __half g_winh  [D_MODEL * D_MLP];
__device__ __half g_wouth [D_MLP * D_MODEL];

// ---------------- helpers ----------------
__device__ __forceinline__ uint32_t smem_u32(const void* p) {
    uint32_t a;
    asm("{ .reg .u64 t; cvta.to.shared.u64 t, %1; cvt.u32.u64 %0, t; }" : "=r"(a) : "l"(p));
    return a;
}
__device__ __forceinline__ float fast_tanh(float x) {
    float y; asm("tanh.approx.f32 %0, %1;" : "=f"(y) : "f"(x)); return y;
}
__device__ __forceinline__ float gelu_new_f(float x) {
    const float c = 0.7978845608028654f;
    float x3 = x * x * x;
    return 0.5f * x * (1.0f + fast_tanh(c * (x + 0.044715f * x3)));
}
__device__ __forceinline__ void mma_f16(float& c0, float& c1, float& c2, float& c3,
                                        uint32_t a0, uint32_t a1, uint32_t a2, uint32_t a3,
                                        uint32_t b0, uint32_t b1) {
    asm volatile(
        "mma.sync.aligned.m16n8k16.row.col.f32.f16.f16.f32 "
        "{%0,%1,%2,%3}, {%4,%5,%6,%7}, {%8,%9}, {%0,%1,%2,%3};\n"
        : "+f"(c0), "+f"(c1), "+f"(c2), "+f"(c3)
        : "r"(a0), "r"(a1), "r"(a2), "r"(a3), "r"(b0), "r"(b1));
}
__device__ __forceinline__ void ldm_x4(uint32_t& r0, uint32_t& r1, uint32_t& r2, uint32_t& r3,
                                       uint32_t a) {
    asm volatile("ldmatrix.sync.aligned.m8n8.x4.shared.b16 {%0,%1,%2,%3}, [%4];"
                 : "=r"(r0), "=r"(r1), "=r"(r2), "=r"(r3) : "r"(a));
}
__device__ __forceinline__ void ldm_x4t(uint32_t& r0, uint32_t& r1, uint32_t& r2, uint32_t& r3,
                                        uint32_t a) {
    asm volatile("ldmatrix.sync.aligned.m8n8.x4.trans.shared.b16 {%0,%1,%2,%3}, [%4];"
                 : "=r"(r0), "=r"(r1), "=r"(r2), "=r"(r3) : "r"(a));
}
__device__ __forceinline__ void cp16(uint32_t dst, const void* src) {
    asm volatile("cp.async.cg.shared.global [%0], [%1], 16;" :: "r"(dst), "l"(src));
}
#define CP_COMMIT() asm volatile("cp.async.commit_group;" ::: "memory")
#define CP_WAIT1()  asm volatile("cp.async.wait_group 1;" ::: "memory")
#define CP_WAIT0()  asm volatile("cp.async.wait_group 0;" ::: "memory")

__device__ __forceinline__ uint32_t h2u(__half2 h) { return *(uint32_t*)&h; }

// combined (sum, sumsq) block reduction for 256 threads
__device__ __forceinline__ float2 block_sum2_256(float a, float b) {
    __shared__ float reda[8], redb[8];
    __shared__ float2 total;
    #pragma unroll
    for (int m = 16; m >= 1; m >>= 1) {
        a += __shfl_xor_sync(0xffffffffu, a, m);
        b += __shfl_xor_sync(0xffffffffu, b, m);
    }
    int w = threadIdx.x >> 5;
    if ((threadIdx.x & 31) == 0) { reda[w] = a; redb[w] = b; }
    __syncthreads();
    if (threadIdx.x < 8) {
        float ta = reda[threadIdx.x], tb = redb[threadIdx.x];
        #pragma unroll
        for (int m = 4; m >= 1; m >>= 1) {
            ta += __shfl_xor_sync(0xffu, ta, m);
            tb += __shfl_xor_sync(0xffu, tb, m);
        }
        if (threadIdx.x == 0) total = make_float2(ta, tb);
    }
    __syncthreads();
    return total;
}

// ---------------- fused weight prep + LN1 ----------------------------------------
#define PK_QKV_BLK 864
#define PK_WO_BLK  288
#define PK_WIN_BLK 1152
#define PK_W_BLK (PK_QKV_BLK + PK_WO_BLK + 2 * PK_WIN_BLK)
#define PK_TOTAL_BLK (PK_W_BLK + ROWS)

__device__ __forceinline__ void f2h_chunk(const float* __restrict__ s,
                                          __half* __restrict__ d, int i) {
    float4 v0 = *(const float4*)(s + (size_t)i * 8);
    float4 v1 = *(const float4*)(s + (size_t)i * 8 + 4);
    __half2 h[4];
    h[0] = __floats2half2_rn(v0.x, v0.y);
    h[1] = __floats2half2_rn(v0.z, v0.w);
    h[2] = __floats2half2_rn(v1.x, v1.y);
    h[3] = __floats2half2_rn(v1.z, v1.w);
    *(uint4*)(d + (size_t)i * 8) = *(uint4*)h;
}

__global__ void prep_all(const float* __restrict__ WQ, const float* __restrict__ WK,
                         const float* __restrict__ WV, const float* __restrict__ bQ,
                         const float* __restrict__ bK, const float* __restrict__ bV,
                         const float* __restrict__ WO, const float* __restrict__ Win,
                         const float* __restrict__ Wout,
                         const float* __restrict__ resid_pre,
                         const float* __restrict__ ln1w, const float* __restrict__ ln1b,
                         __half* __restrict__ Wp, float* __restrict__ bp,
                         __half* __restrict__ woh, __half* __restrict__ winh,
                         __half* __restrict__ wouth, __half* __restrict__ x1h) {
    int blk = blockIdx.x;
    if (blk < PK_QKV_BLK) {
        int idx = blk * 256 + threadIdx.x;
        int hd = (idx & 7) * 8;
        int t  = idx >> 3;
        int e  = t % D_MODEL;
        int t2 = t / D_MODEL;
        int n  = t2 % N_HEADS;
        int which = t2 / N_HEADS;
        const float* W = (which == 0) ? WQ : (which == 1) ? WK : WV;
        const float* src = W + ((size_t)n * D_MODEL + e) * D_HEAD + hd;
        float4 v0 = *(const float4*)(src);
        float4 v1 = *(const float4*)(src + 4);
        __half2 h[4];
        h[0] = __floats2half2_rn(v0.x, v0.y);
        h[1] = __floats2half2_rn(v0.z, v0.w);
        h[2] = __floats2half2_rn(v1.x, v1.y);
        h[3] = __floats2half2_rn(v1.z, v1.w);
        *(uint4*)(Wp + (size_t)e * QKV_N + which * D_MODEL + n * D_HEAD + hd) = *(uint4*)h;
        if (idx < QKV_N) {
            int w2 = idx / D_MODEL;
            int c = idx - w2 * D_MODEL;
            const float* bb = (w2 == 0) ? bQ : (w2 == 1) ? bK : bV;
            bp[idx] = bb[c];
        }
        return;
    }
    blk -= PK_QKV_BLK;
    if (blk < PK_WO_BLK) { f2h_chunk(WO, woh, blk * 256 + threadIdx.x); return; }
    blk -= PK_WO_BLK;
    if (blk < PK_WIN_BLK) { f2h_chunk(Win, winh, blk * 256 + threadIdx.x); return; }
    blk -= PK_WIN_BLK;
    if (blk < PK_WIN_BLK) { f2h_chunk(Wout, wouth, blk * 256 + threadIdx.x); return; }
    blk -= PK_WIN_BLK;
    {
        int row = blk;
        const float* xr = resid_pre + (size_t)row * D_MODEL;
        __half* yr = x1h + (size_t)row * D_MODEL;
        int tid = threadIdx.x;
        float v0 = xr[tid], v1 = xr[tid + 256], v2 = xr[tid + 512];
        float2 ss = block_sum2_256(v0 + v1 + v2, v0 * v0 + v1 * v1 + v2 * v2);
        float mean = ss.x * (1.0f / D_MODEL);
        float var = ss.y * (1.0f / D_MODEL) - mean * mean;
        float rstd = rsqrtf(var + 1e-5f);
        yr[tid]       = __float2half_rn((v0 - mean) * rstd * ln1w[tid]       + ln1b[tid]);
        yr[tid + 256] = __float2half_rn((v1 - mean) * rstd * ln1w[tid + 256] + ln1b[tid + 256]);
        yr[tid + 512] = __float2half_rn((v2 - mean) * rstd * ln1w[tid + 512] + ln1b[tid + 512]);
    }
}

// ---------------- layernorm (LN2) -------------------------------------------------
__global__ void ln_kernel_h(const float* __restrict__ x, const float* __restrict__ w,
                            const float* __restrict__ b, __half* __restrict__ y) {
    int row = blockIdx.x;
    const float* xr = x + (size_t)row * D_MODEL;
    __half* yr = y + (size_t)row * D_MODEL;
    int tid = threadIdx.x;
    float v0 = xr[tid], v1 = xr[tid + 256], v2 = xr[tid + 512];
    float2 ss = block_sum2_256(v0 + v1 + v2, v0 * v0 + v1 * v1 + v2 * v2);
    float mean = ss.x * (1.0f / D_MODEL);
    float var = ss.y * (1.0f / D_MODEL) - mean * mean;
    float rstd = rsqrtf(var + 1e-5f);
    yr[tid]       = __float2half_rn((v0 - mean) * rstd * w[tid]       + b[tid]);
    yr[tid + 256] = __float2half_rn((v1 - mean) * rstd * w[tid + 256] + b[tid + 256]);
    yr[tid + 512] = __float2half_rn((v2 - mean) * rstd * w[tid + 512] + b[tid + 512]);
}

// ---------------- fp16 GEMM, BM=64 x BN=128, 3 CTAs/SM (N=768 GEMMs) -------------
#define G64_STG 24576
#define G64_SMEM (3 * G64_STG)

template<int GELU, int RES, int OUTH>
__global__ __launch_bounds__(256, 3) void gemm_h64(
        const __half* __restrict__ A, const __half* __restrict__ B,
        const float* __restrict__ bias, const float* __restrict__ res,
        void* __restrict__ Cv, int M, int N, int K) {
    extern __shared__ char sm8[];
    const uint32_t sb = smem_u32(sm8);

    const int tid = threadIdx.x;
    const int lane = tid & 31;
    const int wid = tid >> 5;
    const int lr = lane >> 2;
    const int lc = lane & 3;
    const int warp_m = wid & 1;
    const int warp_n = wid >> 1;
    const int bm = blockIdx.y * 64;
    const int bn = blockIdx.x * 128;

    float acc[2][4][4];
    #pragma unroll
    for (int i = 0; i < 2; i++)
        #pragma unroll
        for (int j = 0; j < 4; j++)
            #pragma unroll
            for (int u = 0; u < 4; u++) acc[i][j][u] = 0.0f;

    const int nt = K / 64;

    auto issue = [&](int s, int bk) {
        uint32_t ab = sb + (uint32_t)s * G64_STG;
        #pragma unroll
        for (int i = 0; i < 2; i++) {
            int idx = tid + i * 256;
            int rr = idx >> 3, c = idx & 7;
            cp16(ab + (uint32_t)(rr * 128 + ((c ^ (rr & 7)) * 16)),
                 A + (size_t)(bm + rr) * K + bk + c * 8);
        }
        uint32_t bb = ab + 8192;
        #pragma unroll
        for (int i = 0; i < 4; i++) {
            int idx = tid + i * 256;
            int rr = idx >> 4, c = idx & 15;
            int sc = (c & 8) | ((c ^ rr) & 7);
            cp16(bb + (uint32_t)(rr * 256 + sc * 16),
                 B + (size_t)(bk + rr) * N + bn + c * 8);
        }
    };

    issue(0, 0);  CP_COMMIT();
    issue(1, 64); CP_COMMIT();

    const int j8 = lane >> 3;
    const int li = lane & 7;

    for (int t = 0; t < nt; t++) {
        CP_WAIT1();
        __syncthreads();
        if (t + 2 < nt) issue((t + 2) % 3, (t + 2) * 64);
        CP_COMMIT();

        const uint32_t Ab = sb + (uint32_t)(t % 3) * G64_STG;
        const uint32_t Bb = Ab + 8192;

        #pragma unroll
        for (int ks = 0; ks < 4; ks++) {
            uint32_t a[2][4];
            #pragma unroll
            for (int i = 0; i < 2; i++) {
                int row = warp_m * 32 + i * 16 + (j8 & 1) * 8 + li;
                int chunk = ks * 2 + (j8 >> 1);
                ldm_x4(a[i][0], a[i][1], a[i][2], a[i][3],
                       Ab + (uint32_t)(row * 128 + ((chunk ^ (row & 7)) * 16)));
            }
            uint32_t b[2][4];
            #pragma unroll
            for (int jn = 0; jn < 2; jn++) {
                int krow = ks * 16 + (j8 & 1) * 8 + li;
                int nch = warp_n * 4 + jn * 2 + (j8 >> 1);
                int sc = (nch & 8) | ((nch ^ krow) & 7);
                ldm_x4t(b[jn][0], b[jn][1], b[jn][2], b[jn][3],
                        Bb + (uint32_t)(krow * 256 + sc * 16));
            }
            #pragma unroll
            for (int i = 0; i < 2; i++)
                #pragma unroll
                for (int n8 = 0; n8 < 4; n8++) {
                    int jn = n8 >> 1, sub = n8 & 1;
                    mma_f16(acc[i][n8][0], acc[i][n8][1], acc[i][n8][2], acc[i][n8][3],
                            a[i][0], a[i][1], a[i][2], a[i][3],
                            b[jn][sub * 2], b[jn][sub * 2 + 1]);
                }
        }
        __syncthreads();
    }
    CP_WAIT0();

    float* Cf = (float*)Cv;
    __half* Ch = (__half*)Cv;
    #pragma unroll
    for (int i = 0; i < 2; i++) {
        #pragma unroll
        for (int n8 = 0; n8 < 4; n8++) {
            int r0 = bm + warp_m * 32 + i * 16 + lr;
            int cc = bn + warp_n * 32 + n8 * 8 + lc * 2;
            float2 bv = *(const float2*)&bias[cc];
            #pragma unroll
            for (int hrow = 0; hrow < 2; hrow++) {
                int r = r0 + hrow * 8;
                float o0 = acc[i][n8][hrow * 2]     + bv.x;
                float o1 = acc[i][n8][hrow * 2 + 1] + bv.y;
                if (GELU) { o0 = gelu_new_f(o0); o1 = gelu_new_f(o1); }
                if (RES) {
                    float2 rv = *(const float2*)&res[(size_t)r * N + cc];
                    o0 += rv.x; o1 += rv.y;
                }
                if (OUTH) {
                    __half2 h = __floats2half2_rn(o0, o1);
                    *(__half2*)&Ch[(size_t)r * N + cc] = h;
                } else {
                    *(float2*)&Cf[(size_t)r * N + cc] = make_float2(o0, o1);
                }
            }
        }
    }
}

// ---------------- fp16 GEMM, BM=128 x BN=128, fragment-pipelined, 2 CTAs/SM ------
#define GH_STG 32768
#define GH_SMEM (3 * GH_STG)

template<int GELU, int RES, int OUTH>
__global__ __launch_bounds__(256, 2) void gemm_hp(
        const __half* __restrict__ A, const __half* __restrict__ B,
        const float* __restrict__ bias, const float* __restrict__ res,
        void* __restrict__ Cv, int M, int N, int K) {
    extern __shared__ char sm8[];
    const uint32_t sb = smem_u32(sm8);

    const int tid = threadIdx.x;
    const int lane = tid & 31;
    const int wid = tid >> 5;
    const int lr = lane >> 2;
    const int lc = lane & 3;
    const int warp_m = wid & 1;
    const int warp_n = wid >> 1;
    const int bm = blockIdx.y * 128;
    const int bn = blockIdx.x * 128;

    float acc[4][4][4];
    #pragma unroll
    for (int i = 0; i < 4; i++)
        #pragma unroll
        for (int j = 0; j < 4; j++)
            #pragma unroll
            for (int u = 0; u < 4; u++) acc[i][j][u] = 0.0f;

    const int nt = K / 64;

    auto issue = [&](int s, int bk) {
        uint32_t ab = sb + (uint32_t)s * GH_STG;
        #pragma unroll
        for (int i = 0; i < 4; i++) {
            int idx = tid + i * 256;
            int rr = idx >> 3, c = idx & 7;
            cp16(ab + (uint32_t)(rr * 128 + ((c ^ (rr & 7)) * 16)),
                 A + (size_t)(bm + rr) * K + bk + c * 8);
        }
        uint32_t bb = ab + 16384;
        #pragma unroll
        for (int i = 0; i < 4; i++) {
            int idx = tid + i * 256;
            int rr = idx >> 4, c = idx & 15;
            int sc = (c & 8) | ((c ^ rr) & 7);
            cp16(bb + (uint32_t)(rr * 256 + sc * 16),
                 B + (size_t)(bk + rr) * N + bn + c * 8);
        }
    };

    issue(0, 0);  CP_COMMIT();
    issue(1, 64); CP_COMMIT();

    const int j8 = lane >> 3;
    const int li = lane & 7;

    auto load_a = [&](uint32_t Ab, int ks, uint32_t a[4][4]) {
        #pragma unroll
        for (int i = 0; i < 4; i++) {
            int row = warp_m * 64 + i * 16 + (j8 & 1) * 8 + li;
            int chunk = ks * 2 + (j8 >> 1);
            ldm_x4(a[i][0], a[i][1], a[i][2], a[i][3],
                   Ab + (uint32_t)(row * 128 + ((chunk ^ (row & 7)) * 16)));
        }
    };
    auto load_b = [&](uint32_t Bb, int ks, uint32_t b[2][4]) {
        #pragma unroll
        for (int jn = 0; jn < 2; jn++) {
            int krow = ks * 16 + (j8 & 1) * 8 + li;
            int nch = warp_n * 4 + jn * 2 + (j8 >> 1);
            int sc = (nch & 8) | ((nch ^ krow) & 7);
            ldm_x4t(b[jn][0], b[jn][1], b[jn][2], b[jn][3],
                    Bb + (uint32_t)(krow * 256 + sc * 16));
        }
    };

    for (int t = 0; t < nt; t++) {
        CP_WAIT1();
        __syncthreads();
        if (t + 2 < nt) issue((t + 2) % 3, (t + 2) * 64);
        CP_COMMIT();

        const uint32_t Ab = sb + (uint32_t)(t % 3) * GH_STG;
        const uint32_t Bb = Ab + 16384;

        uint32_t fa[2][4][4];
        uint32_t fb[2][2][4];
        load_a(Ab, 0, fa[0]);
        load_b(Bb, 0, fb[0]);

        #pragma unroll
        for (int ks = 0; ks < 4; ks++) {
            const int cur = ks & 1;
            const int nxt = cur ^ 1;
            if (ks < 3) {
                load_a(Ab, ks + 1, fa[nxt]);
                load_b(Bb, ks + 1, fb[nxt]);
            }
            #pragma unroll
            for (int i = 0; i < 4; i++)
                #pragma unroll
                for (int n8 = 0; n8 < 4; n8++) {
                    int jn = n8 >> 1, sub = n8 & 1;
                    mma_f16(acc[i][n8][0], acc[i][n8][1], acc[i][n8][2], acc[i][n8][3],
                            fa[cur][i][0], fa[cur][i][1], fa[cur][i][2], fa[cur][i][3],
                            fb[cur][jn][sub * 2], fb[cur][jn][sub * 2 + 1]);
                }
        }
        __syncthreads();
    }
    CP_WAIT0();

    float* Cf = (float*)Cv;
    __half* Ch = (__half*)Cv;
    #pragma unroll
    for (int i = 0; i < 4; i++) {
        #pragma unroll
        for (int n8 = 0; n8 < 4; n8++) {
            int r0 = bm + warp_m * 64 + i * 16 + lr;
            int cc = bn + warp_n * 32 + n8 * 8 + lc * 2;
            float2 bv = *(const float2*)&bias[cc];
            #pragma unroll
            for (int hrow = 0; hrow < 2; hrow++) {
                int r = r0 + hrow * 8;
                float o0 = acc[i][n8][hrow * 2]     + bv.x;
                float o1 = acc[i][n8][hrow * 2 + 1] + bv.y;
                if (GELU) { o0 = gelu_new_f(o0); o1 = gelu_new_f(o1); }
                if (RES) {
                    float2 rv = *(const float2*)&res[(size_t)r * N + cc];
                    o0 += rv.x; o1 += rv.y;
                }
                if (OUTH) {
                    __half2 h = __floats2half2_rn(o0, o1);
                    *(__half2*)&Ch[(size_t)r * N + cc] = h;
                } else {
                    *(float2*)&Cf[(size_t)r * N + cc] = make_float2(o0, o1);
                }
            }
        }
    }
}

// ---------------- fp16 MMA flash attention, BQ=64, 3-stage cp.async, 4 CTAs/SM ---
#define A64_Q   8192
#define A64_STG 16384
#define A64_SMEM (A64_Q + 3 * A64_STG)   // 57344 B; 4 CTAs = 224 KB <= 228 KB

__global__ __launch_bounds__(128, 4) void attn_h64_kernel(const __half* __restrict__ qkv,
                                                          __half* __restrict__ z) {
    const int qt = (SEQ / 64 - 1) - blockIdx.x;
    const int bh = blockIdx.y;
    const int b = bh / N_HEADS;
    const int h = bh - b * N_HEADS;

    extern __shared__ char sm8[];
    const uint32_t sb = smem_u32(sm8);
    const uint32_t stg = sb + A64_Q;

    const int tid = threadIdx.x;
    const int lane = tid & 31;
    const int wid = tid >> 5;
    const int lr = lane >> 2;
    const int lc = lane & 3;
    const int j8 = lane >> 3;
    const int li = lane & 7;

    const size_t rowbase = (size_t)b * SEQ;
    const __half* qb = qkv + rowbase * QKV_N + h * 64;
    const __half* kb = qb + D_MODEL;
    const __half* vb = qb + 2 * D_MODEL;

    const int nkt = qt + 1;

    auto issue = [&](int s, int kt) {
        uint32_t base = stg + (uint32_t)s * A64_STG;
        #pragma unroll
        for (int i = 0; i < 4; i++) {
            int idx = tid + i * 128;
            int r = idx >> 3, c = idx & 7;
            uint32_t off = r * 128 + ((c ^ (r & 7)) * 16);
            size_t grow = (size_t)(kt * 64 + r) * QKV_N + c * 8;
            cp16(base + off,        kb + grow);
            cp16(base + 8192 + off, vb + grow);
        }
    };

    // prologue: prefetch stages 0 and 1 while staging Q
    issue(0, 0); CP_COMMIT();
    if (nkt > 1) issue(1, 1);
    CP_COMMIT();

    {
        const __half2 sc2 = __floats2half2_rn(0.125f, 0.125f);
        #pragma unroll
        for (int i = 0; i < 4; i++) {
            int idx = tid + i * 128;
            int r = idx >> 3, c = idx & 7;
            uint4 raw = *(const uint4*)(qb + (size_t)(qt * 64 + r) * QKV_N + c * 8);
            __half2* hp = (__half2*)&raw;
            hp[0] = __hmul2(hp[0], sc2); hp[1] = __hmul2(hp[1], sc2);
            hp[2] = __hmul2(hp[2], sc2); hp[3] = __hmul2(hp[3], sc2);
            *(uint4*)(sm8 + r * 128 + ((c ^ (r & 7)) * 16)) = raw;
        }
    }
    __syncthreads();

    uint32_t qa[4][4];
    {
        int row = wid * 16 + (j8 & 1) * 8 + li;
        uint32_t rb_ = sb + row * 128;
        #pragma unroll
        for (int ks = 0; ks < 4; ks++) {
            int ch = ks * 2 + (j8 >> 1);
            ldm_x4(qa[ks][0], qa[ks][1], qa[ks][2], qa[ks][3],
                   rb_ + ((ch ^ (row & 7)) * 16));
        }
    }

    const int row0 = qt * 64 + wid * 16 + lr;
    const int row1 = row0 + 8;

    float m0 = -INFINITY, m1 = -INFINITY, l0 = 0.0f, l1 = 0.0f;
    float o[8][4];
    #pragma unroll
    for (int n = 0; n < 8; n++) { o[n][0] = o[n][1] = o[n][2] = o[n][3] = 0.0f; }

    for (int kt = 0; kt < nkt; kt++) {
        CP_WAIT1();
        __syncthreads();           // stage kt ready; all compute on stage (kt+2)%3 done
        if (kt + 2 < nkt) issue((kt + 2) % 3, kt + 2);
        CP_COMMIT();

        const uint32_t Kb = stg + (uint32_t)(kt % 3) * A64_STG;
        const uint32_t Vb = Kb + 8192;
        const bool do_mask = (kt == qt);

        #pragma unroll
        for (int hf = 0; hf < 2; hf++) {
            float s[4][4];
            #pragma unroll
            for (int n = 0; n < 4; n++) { s[n][0] = s[n][1] = s[n][2] = s[n][3] = 0.0f; }
            #pragma unroll
            for (int ks = 0; ks < 4; ks++) {
                #pragma unroll
                for (int ng = 0; ng < 2; ng++) {
                    int row = hf * 32 + ng * 16 + (j8 & 1) * 8 + li;
                    int ch = ks * 2 + (j8 >> 1);
                    uint32_t k0, k1, k2, k3;
                    ldm_x4(k0, k1, k2, k3, Kb + row * 128 + ((ch ^ (row & 7)) * 16));
                    mma_f16(s[ng * 2][0], s[ng * 2][1], s[ng * 2][2], s[ng * 2][3],
                            qa[ks][0], qa[ks][1], qa[ks][2], qa[ks][3], k0, k2);
                    mma_f16(s[ng * 2 + 1][0], s[ng * 2 + 1][1], s[ng * 2 + 1][2], s[ng * 2 + 1][3],
                            qa[ks][0], qa[ks][1], qa[ks][2], qa[ks][3], k1, k3);
                }
            }

            if (do_mask) {
                const int kbase = kt * 64 + hf * 32 + lc * 2;
                #pragma unroll
                for (int n8 = 0; n8 < 4; n8++) {
                    int key0 = kbase + n8 * 8;
                    int key1 = key0 + 1;
                    if (key0 > row0) s[n8][0] = -1e30f;
                    if (key1 > row0) s[n8][1] = -1e30f;
                    if (key0 > row1) s[n8][2] = -1e30f;
                    if (key1 > row1) s[n8][3] = -1e30f;
                }
            }

            float tm0 = -INFINITY, tm1 = -INFINITY;
            #pragma unroll
            for (int n8 = 0; n8 < 4; n8++) {
                tm0 = fmaxf(tm0, fmaxf(s[n8][0], s[n8][1]));
                tm1 = fmaxf(tm1, fmaxf(s[n8][2], s[n8][3]));
            }
            tm0 = fmaxf(tm0, __shfl_xor_sync(0xffffffffu, tm0, 1));
            tm0 = fmaxf(tm0, __shfl_xor_sync(0xffffffffu, tm0, 2));
            tm1 = fmaxf(tm1, __shfl_xor_sync(0xffffffffu, tm1, 1));
            tm1 = fmaxf(tm1, __shfl_xor_sync(0xffffffffu, tm1, 2));
            float nm0 = fmaxf(m0, tm0), nm1 = fmaxf(m1, tm1);
            float a0 = __expf(m0 - nm0), a1 = __expf(m1 - nm1);
            m0 = nm0; m1 = nm1;

            float ts0 = 0.0f, ts1 = 0.0f;
            uint32_t ph[4][2];
            #pragma unroll
            for (int n8 = 0; n8 < 4; n8++) {
                float p0 = __expf(s[n8][0] - nm0);
                float p1 = __expf(s[n8][1] - nm0);
                float p2 = __expf(s[n8][2] - nm1);
                float p3 = __expf(s[n8][3] - nm1);
                ts0 += p0 + p1;
                ts1 += p2 + p3;
                ph[n8][0] = h2u(__floats2half2_rn(p0, p1));
                ph[n8][1] = h2u(__floats2half2_rn(p2, p3));
            }
            ts0 += __shfl_xor_sync(0xffffffffu, ts0, 1);
            ts0 += __shfl_xor_sync(0xffffffffu, ts0, 2);
            ts1 += __shfl_xor_sync(0xffffffffu, ts1, 1);
            ts1 += __shfl_xor_sync(0xffffffffu, ts1, 2);
            l0 = l0 * a0 + ts0;
            l1 = l1 * a1 + ts1;
            #pragma unroll
            for (int n8 = 0; n8 < 8; n8++) {
                o[n8][0] *= a0; o[n8][1] *= a0;
                o[n8][2] *= a1; o[n8][3] *= a1;
            }

            #pragma unroll
            for (int ks = 0; ks < 2; ks++) {
                uint32_t pa0 = ph[ks * 2][0];
                uint32_t pa1 = ph[ks * 2][1];
                uint32_t pa2 = ph[ks * 2 + 1][0];
                uint32_t pa3 = ph[ks * 2 + 1][1];
                #pragma unroll
                for (int vg = 0; vg < 4; vg++) {
                    int krow = hf * 32 + ks * 16 + (j8 & 1) * 8 + li;
                    int nch = vg * 2 + (j8 >> 1);
                    uint32_t v0, v1, v2, v3;
                    ldm_x4t(v0, v1, v2, v3, Vb + krow * 128 + ((nch ^ (krow & 7)) * 16));
                    mma_f16(o[vg * 2][0], o[vg * 2][1], o[vg * 2][2], o[vg * 2][3],
                            pa0, pa1, pa2, pa3, v0, v1);
                    mma_f16(o[vg * 2 + 1][0], o[vg * 2 + 1][1], o[vg * 2 + 1][2], o[vg * 2 + 1][3],
                            pa0, pa1, pa2, pa3, v2, v3);
                }
            }
        }
    }
    CP_WAIT0();

    float inv0 = 1.0f / l0, inv1 = 1.0f / l1;
    __half* z0 = z + (rowbase + row0) * D_MODEL + h * 64 + lc * 2;
    __half* z1 = z + (rowbase + row1) * D_MODEL + h * 64 + lc * 2;
    #pragma unroll
    for (int n8 = 0; n8 < 8; n8++) {
        *(__half2*)(z0 + n8 * 8) = __floats2half2_rn(o[n8][0] * inv0, o[n8][1] * inv0);
        *(__half2*)(z1 + n8 * 8) = __floats2half2_rn(o[n8][2] * inv1, o[n8][3] * inv1);
    }
}

// ---------------- launch ----------------
extern "C" void kernel_launch(void* const* d_in, const int* in_sizes, int n_in,
                              void* d_out, int out_size) {
    const float* resid_pre = (const float*)d_in[0];
    const float* WQ   = (const float*)d_in[1];
    const float* bQ   = (const float*)d_in[2];
    const float* WK   = (const float*)d_in[3];
    const float* bK   = (const float*)d_in[4];
    const float* WV   = (const float*)d_in[5];
    const float* bV   = (const float*)d_in[6];
    const float* WO   = (const float*)d_in[7];
    const float* bO   = (const float*)d_in[8];
    const float* ln1w = (const float*)d_in[9];
    const float* ln1b = (const float*)d_in[10];
    const float* ln2w = (const float*)d_in[11];
    const float* ln2b = (const float*)d_in[12];
    const float* Win  = (const float*)d_in[13];
    const float* bin  = (const float*)d_in[14];
    const float* Wout = (const float*)d_in[15];
    const float* bout = (const float*)d_in[16];
    float* out = (float*)d_out;

    __half *x1h, *qkvh, *zh, *x2h, *hidh, *wqkvh, *woh, *winh, *wouth;
    float *mid, *bp;
    cudaGetSymbolAddress((void**)&x1h,    g_x1h);
    cudaGetSymbolAddress((void**)&qkvh,   g_qkvh);
    cudaGetSymbolAddress((void**)&zh,     g_zh);
    cudaGetSymbolAddress((void**)&mid,    g_mid);
    cudaGetSymbolAddress((void**)&x2h,    g_x2h);
    cudaGetSymbolAddress((void**)&hidh,   g_hidh);
    cudaGetSymbolAddress((void**)&wqkvh,  g_wqkvh);
    cudaGetSymbolAddress((void**)&bp,     g_bqkv);
    cudaGetSymbolAddress((void**)&woh,    g_woh);
    cudaGetSymbolAddress((void**)&winh,   g_winh);
    cudaGetSymbolAddress((void**)&wouth,  g_wouth);

    cudaFuncSetAttribute(attn_h64_kernel, cudaFuncAttributeMaxDynamicSharedMemorySize, A64_SMEM);
    cudaFuncSetAttribute(gemm_hp<0,0,1>,  cudaFuncAttributeMaxDynamicSharedMemorySize, GH_SMEM);
    cudaFuncSetAttribute(gemm_hp<1,0,1>,  cudaFuncAttributeMaxDynamicSharedMemorySize, GH_SMEM);
    cudaFuncSetAttribute(gemm_h64<0,1,0>, cudaFuncAttributeMaxDynamicSharedMemorySize, G64_SMEM);

    // fused weight prep + LN1 (single launch)
    prep_all<<<PK_TOTAL_BLK, 256>>>(WQ, WK, WV, bQ, bK, bV, WO, Win, Wout,
                                    resid_pre, ln1w, ln1b,
                                    wqkvh, bp, woh, winh, wouth, x1h);

    // QKV projection -> half (BM=128, fragment-pipelined)
    gemm_hp<0,0,1><<<dim3(QKV_N / 128, ROWS / 128), 256, GH_SMEM>>>(
        x1h, wqkvh, bp, nullptr, qkvh, ROWS, QKV_N, D_MODEL);
    // attention -> half z (BQ=64, 3-stage, 4 CTAs/SM)
    attn_h64_kernel<<<dim3(SEQ / 64, BATCH * N_HEADS), 128, A64_SMEM>>>(qkvh, zh);
    // O projection + residual -> float mid (BM=64, single wave)
    gemm_h64<0,1,0><<<dim3(D_MODEL / 128, ROWS / 64), 256, G64_SMEM>>>(
        zh, woh, bO, resid_pre, mid, ROWS, D_MODEL, D_MODEL);
    // LN2 -> half
    ln_kernel_h<<<ROWS, 256>>>(mid, ln2w, ln2b, x2h);
    // MLP up + gelu -> half (BM=128, fragment-pipelined)
    gemm_hp<1,0,1><<<dim3(D_MLP / 128, ROWS / 128), 256, GH_SMEM>>>(
        x2h, winh, bin, nullptr, hidh, ROWS, D_MLP, D_MODEL);
    // MLP down + residual -> float out (BM=64, single wave)
    gemm_h64<0,1,0><<<dim3(D_MODEL / 128, ROWS / 64), 256, G64_SMEM>>>(
        hidh, wouth, bout, mid, out, ROWS, D_MODEL, D_MLP);
}